// round 11
// baseline (speedup 1.0000x reference)
#include <cuda_runtime.h>
#include <cuda_bf16.h>

// feeds: [N=65536, D=512] f32, rep: [N] int32 in [0,8), out: [S=262144, D] f32.
// out row j = feeds[i] where cumsum(rep) first exceeds j; rows >= total are 0.
//
// ONE fused launch:
//   blocks [0,64):        scan segment of 1024 reps -> g_cum, publish flagB
//   blocks [64, 64+N):    scatter one row (prefetch row, spin on seg flag,
//                         then r coalesced 2KB __stcs stores)
//   blocks [64+N, end):   zero tail [total, S)
//   every block counts; the last one re-arms flags/counter for graph replay.

#define MAX_N 65536
#define SCAN_BLOCKS 64
#define TAIL_BLOCKS 2048

__device__ __align__(16) int g_cum[MAX_N];
__device__ int g_bsum[SCAN_BLOCKS];
__device__ volatile int g_flagA[SCAN_BLOCKS];   // aggregate published
__device__ volatile int g_flagB[SCAN_BLOCKS];   // segment cum published
__device__ unsigned int g_consumed;             // zero-init; self-resetting

__global__ void fused_kernel(const float4* __restrict__ feeds,
                             const int* __restrict__ rep,
                             float4* __restrict__ out,
                             int d4, int N, size_t n4, unsigned nblocks) {
    const int b = blockIdx.x;
    const int tid = threadIdx.x;

    if (b < SCAN_BLOCKS) {
        // ---- scan of segment b: 1024 ints, 128 threads, 8 items/thread ----
        __shared__ int wsum[4];
        __shared__ int s_off;
        const int lane = tid & 31, wid = tid >> 5;
        const int4* rp = (const int4*)(rep + b * 1024) + tid * 2;
        const int4 a = __ldg(rp), c = __ldg(rp + 1);
        const int s0 = a.x,      s1 = s0 + a.y, s2 = s1 + a.z, s3 = s2 + a.w;
        const int s4 = s3 + c.x, s5 = s4 + c.y, s6 = s5 + c.z, s7 = s6 + c.w;
        const int tot = s7;

        int inc = tot;                       // warp-inclusive scan of totals
        #pragma unroll
        for (int off = 1; off < 32; off <<= 1) {
            int y = __shfl_up_sync(0xffffffffu, inc, off);
            if (lane >= off) inc += y;
        }
        const int texcl = inc - tot;         // exclusive prefix within warp
        if (lane == 31) wsum[wid] = inc;     // warp total
        __syncthreads();

        // Publish block aggregate, then lookback over predecessors (warp 0).
        if (tid == 0) {
            g_bsum[b] = wsum[0] + wsum[1] + wsum[2] + wsum[3];
            __threadfence();
            g_flagA[b] = 1;
        }
        if (wid == 0) {
            int v = 0;
            if (lane < b)      { while (g_flagA[lane] == 0) __nanosleep(20);
                                 v += g_bsum[lane]; }
            if (lane + 32 < b) { while (g_flagA[lane + 32] == 0) __nanosleep(20);
                                 v += g_bsum[lane + 32]; }
            #pragma unroll
            for (int off = 16; off > 0; off >>= 1)
                v += __shfl_down_sync(0xffffffffu, v, off);
            if (lane == 0) s_off = v;
        }
        // per-thread warp offset (<=3 adds, no extra sync needed: wsum is
        // already published and s_off arrives at the next barrier)
        int wo = 0;
        #pragma unroll
        for (int w = 0; w < 4; w++) if (w < wid) wo += wsum[w];
        __syncthreads();                     // publishes s_off

        const int base = s_off + wo + texcl;
        int4* cp = (int4*)g_cum + b * 256 + tid * 2;
        cp[0] = make_int4(s0 + base, s1 + base, s2 + base, s3 + base);
        cp[1] = make_int4(s4 + base, s5 + base, s6 + base, s7 + base);
        __syncthreads();
        if (tid == 0) {
            __threadfence();
            g_flagB[b] = 1;
            __threadfence();
        }
    } else if (b < SCAN_BLOCKS + N) {
        // ---- scatter one source row ----
        const int rb = b - SCAN_BLOCKS;
        const int r = __ldg(rep + rb);
        if (r > 0) {
            // Prefetch the row (independent of the scan) before waiting.
            const float4 v = feeds[(size_t)rb * d4 + tid];
            const int seg = rb >> 10;
            if (tid == 0)
                while (g_flagB[seg] == 0) __nanosleep(40);
            __syncthreads();
            const int start = __ldcg(&g_cum[rb]) - r;
            float4* dst = out + (size_t)start * d4 + tid;
            for (int k = 0; k < r; k++)
                __stcs(dst + (size_t)k * d4, v);
        }
    } else {
        // ---- zero tail [total*d4, n4) ----
        if (tid == 0)
            while (g_flagB[SCAN_BLOCKS - 1] == 0) __nanosleep(40);
        __syncthreads();
        const int total = __ldcg(&g_cum[N - 1]);
        const size_t begin = (size_t)total * d4;
        const size_t tb = b - (SCAN_BLOCKS + N);
        const size_t stride = (size_t)TAIL_BLOCKS * blockDim.x;
        const float4 z = make_float4(0.f, 0.f, 0.f, 0.f);
        for (size_t i = begin + tb * blockDim.x + tid; i < n4; i += stride)
            __stcs(out + i, z);
    }

    // ---- completion count; last block re-arms flags for the next replay ----
    if (tid == 0) {
        __threadfence();
        const unsigned old = atomicAdd(&g_consumed, 1u);
        if (old == nblocks - 1u) {
            __threadfence();
            for (int i = 0; i < SCAN_BLOCKS; i++) {
                g_flagA[i] = 0;
                g_flagB[i] = 0;
            }
            __threadfence();
            g_consumed = 0u;
        }
    }
}

extern "C" void kernel_launch(void* const* d_in, const int* in_sizes, int n_in,
                              void* d_out, int out_size) {
    const float4* feeds = (const float4*)d_in[0];
    const int*    rep   = (const int*)d_in[1];
    float4*       out   = (float4*)d_out;

    const int N = in_sizes[1];                 // 65536 source rows
    const int D = in_sizes[0] / N;             // 512
    const int d4 = D / 4;                      // 128 float4 per row
    const int S = out_size / D;                // 262144 output rows
    const size_t n4 = (size_t)S * d4;

    const unsigned nblocks = SCAN_BLOCKS + N + TAIL_BLOCKS;
    fused_kernel<<<nblocks, d4>>>(feeds, rep, out, d4, N, n4, nblocks);
}

// round 12
// speedup vs baseline: 1.0606x; 1.0606x over previous
#include <cuda_runtime.h>
#include <cuda_bf16.h>

// feeds: [N=65536, D=512] f32, rep: [N] int32 in [0,8), out: [S=262144, D] f32.
// out row j = feeds[i] where cumsum(rep) first exceeds j; rows >= total are 0.
//
// Pipeline (R9 kernels + PDL chaining so launches overlap execution):
//   1) block_sum_kernel: 64 blocks x 256 (int4) -> g_blocksum[64]
//   2) scan_kernel (PDL): own-segment scan overlaps #1; griddepsync before
//      reading g_blocksum; -> g_cum
//   3) scatter_kernel (PDL): prefetch feeds row overlapping #2; griddepsync
//      before reading g_cum; r coalesced 2KB __stcs stores; tail zeroing.

#define MAX_N 65536
#define SCAN_BLOCKS 64
__device__ int g_cum[MAX_N];
__device__ int g_blocksum[SCAN_BLOCKS];

// 64 blocks x 256 threads, each thread sums one int4 (block covers 1024 ints).
__global__ void block_sum_kernel(const int4* __restrict__ rep4) {
    __shared__ int ws[8];
    const int tid = threadIdx.x;
    const int lane = tid & 31, wid = tid >> 5;
    const int4 v = __ldg(rep4 + blockIdx.x * 256 + tid);
    int x = v.x + v.y + v.z + v.w;
    #pragma unroll
    for (int off = 16; off > 0; off >>= 1)
        x += __shfl_down_sync(0xffffffffu, x, off);
    if (lane == 0) ws[wid] = x;
    __syncthreads();
    if (wid == 0 && lane < 8) {
        int w = ws[lane];
        #pragma unroll
        for (int off = 4; off > 0; off >>= 1)
            w += __shfl_down_sync(0x000000ffu, w, off);
        if (lane == 0) g_blocksum[blockIdx.x] = w;
    }
}

__global__ void scan_kernel(const int* __restrict__ rep) {
    __shared__ int ws[32];
    __shared__ int s_off;
    const int tid = threadIdx.x;
    const int lane = tid & 31, wid = tid >> 5;
    const int b = blockIdx.x;

    // Phase 1 (overlaps block_sum): own-item warp scan — reads input only.
    const int idx = b * 1024 + tid;
    int x = __ldg(rep + idx);
    #pragma unroll
    for (int off = 1; off < 32; off <<= 1) {
        int y = __shfl_up_sync(0xffffffffu, x, off);
        if (lane >= off) x += y;
    }
    if (lane == 31) ws[wid] = x;

    // Wait for block_sum_kernel's g_blocksum writes to be visible.
    cudaGridDependencySynchronize();
    __syncthreads();

    if (wid == 0) {
        // Offset = sum of g_blocksum[0..b): predicated loads, full-warp red.
        int v = 0;
        if (lane < b) v += __ldg(&g_blocksum[lane]);
        if (lane + 32 < b) v += __ldg(&g_blocksum[lane + 32]);
        #pragma unroll
        for (int off = 16; off > 0; off >>= 1)
            v += __shfl_down_sync(0xffffffffu, v, off);
        if (lane == 0) s_off = v;
        // Cross-warp inclusive scan of warp totals.
        int w = ws[lane];
        #pragma unroll
        for (int off = 1; off < 32; off <<= 1) {
            int y = __shfl_up_sync(0xffffffffu, w, off);
            if (lane >= off) w += y;
        }
        ws[lane] = w;
    }
    __syncthreads();

    g_cum[idx] = x + (wid > 0 ? ws[wid - 1] : 0) + s_off;
    cudaTriggerProgrammaticLaunchCompletion();
}

// blocks [0, N): one per source row, 128 threads x float4 = one 2KB row.
// blocks [N, N+TAIL_BLOCKS): grid-stride zero of [total*d4, n4).
#define TAIL_BLOCKS 2048
__global__ void scatter_kernel(const float4* __restrict__ feeds,
                               const int* __restrict__ rep,
                               float4* __restrict__ out, int d4, int N,
                               size_t n4) {
    const int b = blockIdx.x;
    if (b < N) {
        const int r = __ldg(rep + b);
        // Prefetch the row (inputs only) while the scan may still be running.
        float4 v;
        if (r > 0) v = feeds[(size_t)b * d4 + threadIdx.x];
        cudaGridDependencySynchronize();   // g_cum now visible
        if (r == 0) return;
        const int start = g_cum[b] - r;
        float4* dst = out + (size_t)start * d4 + threadIdx.x;
        for (int k = 0; k < r; k++)
            __stcs(dst + (size_t)k * d4, v);
    } else {
        cudaGridDependencySynchronize();
        const int total = g_cum[N - 1];
        const size_t begin = (size_t)total * d4;
        const size_t tb = b - N;
        const size_t stride = (size_t)TAIL_BLOCKS * blockDim.x;
        const float4 z = make_float4(0.f, 0.f, 0.f, 0.f);
        for (size_t i = begin + tb * blockDim.x + threadIdx.x; i < n4;
             i += stride)
            __stcs(out + i, z);
    }
}

extern "C" void kernel_launch(void* const* d_in, const int* in_sizes, int n_in,
                              void* d_out, int out_size) {
    const float4* feeds = (const float4*)d_in[0];
    const int*    rep   = (const int*)d_in[1];
    float4*       out   = (float4*)d_out;

    const int N = in_sizes[1];                 // 65536 source rows
    const int D = in_sizes[0] / N;             // 512
    const int d4 = D / 4;                      // 128 float4 per row
    const int S = out_size / D;                // 262144 output rows
    const size_t n4 = (size_t)S * d4;

    // 1) block_sum: plain launch.
    block_sum_kernel<<<SCAN_BLOCKS, 256>>>((const int4*)rep);

    // 2) scan: PDL — may start while block_sum runs; griddepsyncs internally.
    {
        cudaLaunchConfig_t cfg = {};
        cfg.gridDim = dim3(SCAN_BLOCKS);
        cfg.blockDim = dim3(1024);
        cudaLaunchAttribute at[1];
        at[0].id = cudaLaunchAttributeProgrammaticStreamSerialization;
        at[0].val.programmaticStreamSerializationAllowed = 1;
        cfg.attrs = at;
        cfg.numAttrs = 1;
        cudaLaunchKernelEx(&cfg, scan_kernel, rep);
    }

    // 3) scatter: PDL — prefetch overlaps scan; griddepsyncs before g_cum.
    {
        cudaLaunchConfig_t cfg = {};
        cfg.gridDim = dim3(N + TAIL_BLOCKS);
        cfg.blockDim = dim3(d4);
        cudaLaunchAttribute at[1];
        at[0].id = cudaLaunchAttributeProgrammaticStreamSerialization;
        at[0].val.programmaticStreamSerializationAllowed = 1;
        cfg.attrs = at;
        cfg.numAttrs = 1;
        cudaLaunchKernelEx(&cfg, scatter_kernel, feeds, rep, out, d4, N, n4);
    }
}